// round 1
// baseline (speedup 1.0000x reference)
#include <cuda_runtime.h>
#include <stdint.h>

// Problem constants (fixed by the dataset).
#define NN 100000
#define NE 1000000
#define HDIM 128
#define NHEADS 4

// ---------------- device scratch (no allocations allowed) ----------------
__device__ float         g_acc[NN];        // segment-sum accumulator
__device__ double        g_loss;           // squared-error accumulator
__device__ unsigned char g_ncodes[NN];     // 4-bit node codes
__device__ unsigned char g_ecodes[NE];     // 4-bit edge codes
__device__ float         g_TE[NHEADS][16]; // edge-emb tables (pre-divided by tau)
__device__ float         g_TN[NHEADS][16]; // node-emb tables (pre-divided by tau)
__device__ float         g_Cc[NHEADS];     // constant term per head (pre-divided by tau)

// ---------------- kernel 1: zero scratch ----------------
__global__ void zero_kernel() {
    int i = blockIdx.x * blockDim.x + threadIdx.x;
    if (i < NN) g_acc[i] = 0.0f;
    if (i == 0) g_loss = 0.0;
}

// ---------------- kernel 2: compress binary states to codes ----------------
__global__ void codes_kernel(const int* __restrict__ node_states,
                             const int* __restrict__ edge_states) {
    int i = blockIdx.x * blockDim.x + threadIdx.x;
    if (i < NN) {
        int4 s = reinterpret_cast<const int4*>(node_states)[i];
        g_ncodes[i] = (unsigned char)(s.x + 2 * s.y + 4 * s.z + 8 * s.w);
    }
    int e = i - NN;
    if (e >= 0 && e < NE) {
        int4 s = reinterpret_cast<const int4*>(edge_states)[e];
        g_ecodes[e] = (unsigned char)(s.x + 2 * s.y + 4 * s.z + 8 * s.w);
    }
}

// ---------------- kernel 3: build per-head lookup tables ----------------
// One block of 128 threads. Head order: 0=increment, 1=keep, 2=push(wo), 3=push_node(w).
__global__ void table_kernel(const float* __restrict__ combine_W,   // (256,128)
                             const float* __restrict__ combine_b,   // (128,)
                             const float* __restrict__ node_emb,    // (16,128)
                             const float* __restrict__ edge_emb,    // (16,128)
                             const float* __restrict__ keep_W, const float* __restrict__ keep_b,
                             const float* __restrict__ push_W, const float* __restrict__ push_b,
                             const float* __restrict__ pushn_W, const float* __restrict__ pushn_b,
                             const float* __restrict__ inc_W, const float* __restrict__ inc_b,
                             const int* __restrict__ training_step) {
    __shared__ float sh_d[HDIM];
    __shared__ float sh_u[2 * HDIM];   // [0:128) = u_edge, [128:256) = u_node
    int tid = threadIdx.x;

    // tau(step): step==-1 -> 0.1 ; else 1 + (0.1-1)*min(step/10000, 1)
    int step = training_step[0];
    float tau = (step == -1) ? 0.1f
              : (1.0f + (0.1f - 1.0f) * fminf((float)step / 10000.0f, 1.0f));
    float invtau = 1.0f / tau;

    const float* Wh[NHEADS] = {inc_W, keep_W, push_W, pushn_W};
    const float* bh[NHEADS] = {inc_b, keep_b, push_b, pushn_b};

    for (int h = 0; h < NHEADS; h++) {
        // d = W[:,0] - W[:,1]   (W is row-major (128,2))
        float d = Wh[h][tid * 2] - Wh[h][tid * 2 + 1];
        sh_d[tid] = d;
        __syncthreads();

        // u_e[i] = sum_c combine_W[i, c]        * d[c]
        // u_n[i] = sum_c combine_W[128 + i, c]  * d[c]
        float ue = 0.0f, un = 0.0f;
        #pragma unroll 8
        for (int c = 0; c < HDIM; c++) {
            float dc = sh_d[c];
            ue += combine_W[tid * HDIM + c] * dc;
            un += combine_W[(HDIM + tid) * HDIM + c] * dc;
        }
        sh_u[tid] = ue;
        sh_u[HDIM + tid] = un;
        __syncthreads();

        if (tid < 16) {
            float t = 0.0f;
            #pragma unroll 8
            for (int i = 0; i < HDIM; i++) t += edge_emb[tid * HDIM + i] * sh_u[i];
            g_TE[h][tid] = t * invtau;
        } else if (tid < 32) {
            int k = tid - 16;
            float t = 0.0f;
            #pragma unroll 8
            for (int i = 0; i < HDIM; i++) t += node_emb[k * HDIM + i] * sh_u[HDIM + i];
            g_TN[h][k] = t * invtau;
        } else if (tid == 32) {
            float c0 = 0.0f;
            for (int i = 0; i < HDIM; i++) c0 += combine_b[i] * sh_d[i];
            g_Cc[h] = (c0 + bh[h][0] - bh[h][1]) * invtau;
        }
        __syncthreads();   // protect sh_d before next head overwrites it
    }
}

// ---------------- kernel 4: main edge pass ----------------
__global__ void __launch_bounds__(256) pass1_kernel(const int* __restrict__ edge_index,   // (2,E)
                                                    const int* __restrict__ brev,         // (E,)
                                                    const float* __restrict__ scalars,    // (E,)
                                                    float* __restrict__ out) {
    __shared__ float sTE[NHEADS][16], sTN[NHEADS][16], sC[NHEADS];
    int tid = threadIdx.x;
    if (tid < NHEADS * 16) {
        int h = tid >> 4, k = tid & 15;
        sTE[h][k] = g_TE[h][k];
        sTN[h][k] = g_TN[h][k];
        if (k == 0) sC[h] = g_Cc[h];
    }
    __syncthreads();

    int e = blockIdx.x * blockDim.x + tid;
    if (e >= NE) return;

    int rev = brev[e];
    int src = edge_index[e];
    int dst = edge_index[NE + e];
    int ce = g_ecodes[rev];
    int cn = g_ncodes[src];

    float s    = scalars[e];
    float ssrc = __ldg(&scalars[src]);   // node_scalars = scalars[:N]
    float sdst = __ldg(&scalars[dst]);

    float p[NHEADS];
    #pragma unroll
    for (int h = 0; h < NHEADS; h++) {
        float logit = sTE[h][ce] + sTN[h][cn] + sC[h];
        p[h] = 1.0f / (1.0f + __expf(-logit));
    }

    float s_wo = s - sdst;
    float s_w  = s_wo + ssrc;
    atomicAdd(&g_acc[dst], p[2] * s_wo + p[3] * s_w);

    out[e] = p[0] + s * p[1];   // increment + keep (push added in pass2)
}

// ---------------- kernel 5: finalize scalars + loss reduction ----------------
__global__ void __launch_bounds__(256) pass2_kernel(const float* __restrict__ target,  // batch_scalars (E,)
                                                    float* __restrict__ out) {
    __shared__ float warp_sums[8];
    int e = blockIdx.x * blockDim.x + threadIdx.x;

    float sq = 0.0f;
    if (e < NE) {
        float ns = out[e];
        if (e < NN) ns += g_acc[e];
        out[e] = ns;
        float d = target[e] - ns;
        sq = d * d;
    }

    // block reduce
    #pragma unroll
    for (int o = 16; o > 0; o >>= 1) sq += __shfl_down_sync(0xFFFFFFFFu, sq, o);
    int lane = threadIdx.x & 31, wid = threadIdx.x >> 5;
    if (lane == 0) warp_sums[wid] = sq;
    __syncthreads();
    if (wid == 0) {
        float v = (lane < 8) ? warp_sums[lane] : 0.0f;
        #pragma unroll
        for (int o = 4; o > 0; o >>= 1) v += __shfl_down_sync(0xFFFFFFFFu, v, o);
        if (lane == 0) atomicAdd(&g_loss, (double)v);
    }
}

__global__ void finalize_kernel(float* __restrict__ out) {
    out[NE] = (float)(g_loss / (double)NE);
}

// ---------------- launcher ----------------
extern "C" void kernel_launch(void* const* d_in, const int* in_sizes, int n_in,
                              void* d_out, int out_size) {
    const int*   node_states = (const int*)  d_in[0];
    const int*   edge_states = (const int*)  d_in[1];
    const float* scalars     = (const float*)d_in[2];
    const int*   edge_index  = (const int*)  d_in[3];
    const int*   brev        = (const int*)  d_in[4];
    const float* batch_sc    = (const float*)d_in[5];
    // d_in[6] = processor_step (must be 0; batch_scalars middle dim is 1)
    const int*   train_step  = (const int*)  d_in[7];
    const float* node_emb    = (const float*)d_in[8];
    const float* edge_emb    = (const float*)d_in[9];
    const float* combine_W   = (const float*)d_in[10];
    const float* combine_b   = (const float*)d_in[11];
    const float* keep_W      = (const float*)d_in[12];
    const float* keep_b      = (const float*)d_in[13];
    const float* push_W      = (const float*)d_in[14];
    const float* push_b      = (const float*)d_in[15];
    const float* pushn_W     = (const float*)d_in[16];
    const float* pushn_b     = (const float*)d_in[17];
    const float* inc_W       = (const float*)d_in[18];
    const float* inc_b       = (const float*)d_in[19];

    float* out = (float*)d_out;

    zero_kernel<<<(NN + 255) / 256, 256>>>();
    codes_kernel<<<(NN + NE + 255) / 256, 256>>>(node_states, edge_states);
    table_kernel<<<1, 128>>>(combine_W, combine_b, node_emb, edge_emb,
                             keep_W, keep_b, push_W, push_b,
                             pushn_W, pushn_b, inc_W, inc_b, train_step);
    pass1_kernel<<<(NE + 255) / 256, 256>>>(edge_index, brev, scalars, out);
    pass2_kernel<<<(NE + 255) / 256, 256>>>(batch_sc, out);
    if (out_size > NE) finalize_kernel<<<1, 1>>>(out);
}

// round 2
// speedup vs baseline: 3.6967x; 3.6967x over previous
#include <cuda_runtime.h>
#include <stdint.h>

#define NN 100000
#define NE 1000000
#define HDIM 128
#define NHEADS 4

// ---------------- device scratch ----------------
__device__ float2        g_acc2[NN];       // per-dst {A, B}: acc = A - scalars[d]*B
__device__ double        g_loss;
__device__ int2          g_nrec[NN];       // {float_as_int(scalars[i]), node_code}
__device__ unsigned char g_ecodes[NE];
__device__ float         g_M[32][HDIM];    // rows 0-15: edge_emb@Wtop, 16-31: node_emb@Wbot
__device__ float         g_P[NHEADS][256]; // sigmoid prob tables over (ce<<4)|cn
__device__ unsigned      g_cnt1 = 0;       // tables-kernel completion counter
__device__ unsigned      g_done = 0;       // pass2 completion counter

// vector reduction (no return) — one scattered op instead of two
__device__ __forceinline__ void red_add_f2(float2* addr, float a, float b) {
    asm volatile("red.global.add.v2.f32 [%0], {%1, %2};"
                 :: "l"(addr), "f"(a), "f"(b) : "memory");
}

// ---------------- kernel 1: prep (codes + node records + zeroing) ----------------
__global__ void __launch_bounds__(256) prep_kernel(const int* __restrict__ node_states,
                                                   const int* __restrict__ edge_states,
                                                   const float* __restrict__ scalars) {
    int i = blockIdx.x * blockDim.x + threadIdx.x;
    if (i < NE) {
        int4 s = reinterpret_cast<const int4*>(edge_states)[i];
        g_ecodes[i] = (unsigned char)(s.x + 2 * s.y + 4 * s.z + 8 * s.w);
    }
    if (i < NN) {
        int4 s = reinterpret_cast<const int4*>(node_states)[i];
        int2 nr;
        nr.x = __float_as_int(scalars[i]);
        nr.y = s.x + 2 * s.y + 4 * s.z + 8 * s.w;
        g_nrec[i] = nr;
        g_acc2[i] = make_float2(0.0f, 0.0f);
    }
    if (i == 0) g_loss = 0.0;
}

// ---------------- kernel 2: tables (32 blocks; last block finishes) ----------------
__global__ void __launch_bounds__(128) tables_kernel(
        const float* __restrict__ combine_W,   // (256,128)
        const float* __restrict__ combine_b,   // (128,)
        const float* __restrict__ node_emb,    // (16,128)
        const float* __restrict__ edge_emb,    // (16,128)
        const float* __restrict__ keep_W,  const float* __restrict__ keep_b,
        const float* __restrict__ push_W,  const float* __restrict__ push_b,
        const float* __restrict__ pushn_W, const float* __restrict__ pushn_b,
        const float* __restrict__ inc_W,   const float* __restrict__ inc_b,
        const int* __restrict__ training_step) {
    int tid = threadIdx.x;
    int b = blockIdx.x;                 // 0..31
    int k = b & 15;
    int base = (b < 16) ? 0 : HDIM;
    const float* embrow = ((b < 16) ? edge_emb : node_emb) + k * HDIM;

    __shared__ float sh_emb[HDIM];
    sh_emb[tid] = embrow[tid];
    __syncthreads();

    // M[b][tid] = sum_i emb[i] * combine_W[base+i][tid]  (coalesced over tid)
    float a = 0.0f;
    #pragma unroll 8
    for (int i = 0; i < HDIM; i++)
        a = fmaf(sh_emb[i], combine_W[(base + i) * HDIM + tid], a);
    g_M[b][tid] = a;

    // fence + count; last-arriving block computes the head tables
    __shared__ int sh_last;
    __threadfence();
    if (tid == 0) sh_last = (atomicAdd(&g_cnt1, 1u) == 31u);
    __syncthreads();
    if (!sh_last) return;

    // stage M into padded shared (conflict-free row-per-lane reads)
    __shared__ float shM[32][HDIM + 1];
    for (int r = 0; r < 32; r++) shM[r][tid] = g_M[r][tid];

    // per-head direction vectors d_h = W[:,0]-W[:,1]
    __shared__ float shd[NHEADS][HDIM];
    __shared__ float shTE[NHEADS][16], shTN[NHEADS][16], shC[NHEADS];
    const float* Wh[NHEADS] = {inc_W, keep_W, push_W, pushn_W};
    const float* bh[NHEADS] = {inc_b, keep_b, push_b, pushn_b};
    #pragma unroll
    for (int h = 0; h < NHEADS; h++)
        shd[h][tid] = Wh[h][2 * tid] - Wh[h][2 * tid + 1];
    __syncthreads();

    int step = training_step[0];
    float tau = (step == -1) ? 0.1f
              : (1.0f + (0.1f - 1.0f) * fminf((float)step / 10000.0f, 1.0f));
    float invtau = 1.0f / tau;

    int h = tid >> 5, j = tid & 31;     // 4 heads x 32 outputs
    const float* dv = shd[h];
    {
        int row = (j < 16) ? j : (16 + (j - 16));   // == j; rows 0-15 TE, 16-31 TN
        float t = 0.0f;
        #pragma unroll 8
        for (int i = 0; i < HDIM; i++) t = fmaf(shM[row][i], dv[i], t);
        t *= invtau;
        if (j < 16) shTE[h][j] = t; else shTN[h][j - 16] = t;
    }
    if (j == 0) {
        float c = 0.0f;
        for (int i = 0; i < HDIM; i++) c = fmaf(combine_b[i], dv[i], c);
        shC[h] = (c + bh[h][0] - bh[h][1]) * invtau;
    }
    __syncthreads();

    // bake 4 x 256 sigmoid tables: P[h][(ce<<4)|cn]
    for (int t = tid; t < NHEADS * 256; t += 128) {
        int hh = t >> 8, cc = t & 255;
        float logit = shTE[hh][cc >> 4] + shTN[hh][cc & 15] + shC[hh];
        g_P[hh][cc] = 1.0f / (1.0f + __expf(-logit));
    }
    if (tid == 0) g_cnt1 = 0;   // reset for next graph replay
}

// ---------------- kernel 3: main edge pass ----------------
__global__ void __launch_bounds__(256) pass1_kernel(const int* __restrict__ edge_index,
                                                    const int* __restrict__ brev,
                                                    const float* __restrict__ scalars,
                                                    const float* __restrict__ target,
                                                    float* __restrict__ out) {
    __shared__ float sP[NHEADS][256];
    __shared__ float warp_sums[8];
    int tid = threadIdx.x;
    #pragma unroll
    for (int t = tid; t < NHEADS * 256; t += 256)
        sP[t >> 8][t & 255] = g_P[t >> 8][t & 255];
    __syncthreads();

    int e = blockIdx.x * blockDim.x + tid;
    float sq = 0.0f;
    if (e < NE) {
        int rev = brev[e];
        int src = edge_index[e];
        int dst = edge_index[NE + e];
        float s = scalars[e];

        unsigned ce = g_ecodes[rev];          // scattered byte gather
        int2 nr = g_nrec[src];                // scattered 8B gather
        float ssrc = __int_as_float(nr.x);
        unsigned cc = (ce << 4) | (unsigned)nr.y;

        float p0 = sP[0][cc], p1 = sP[1][cc], p2 = sP[2][cc], p3 = sP[3][cc];

        float pw = p2 + p3;
        red_add_f2(&g_acc2[dst], fmaf(pw, s, p3 * ssrc), pw);  // scattered v2 red

        float ns = fmaf(s, p1, p0);           // increment + keep
        out[e] = ns;
        if (e >= NN) {                         // edge_push==0 here -> final; do loss now
            float d = target[e] - ns;
            sq = d * d;
        }
    }

    // block reduce -> g_loss
    #pragma unroll
    for (int o = 16; o > 0; o >>= 1) sq += __shfl_down_sync(0xFFFFFFFFu, sq, o);
    int lane = tid & 31, wid = tid >> 5;
    if (lane == 0) warp_sums[wid] = sq;
    __syncthreads();
    if (wid == 0) {
        float v = (lane < 8) ? warp_sums[lane] : 0.0f;
        #pragma unroll
        for (int o = 4; o > 0; o >>= 1) v += __shfl_down_sync(0xFFFFFFFFu, v, o);
        if (lane == 0 && v != 0.0f) atomicAdd(&g_loss, (double)v);
    }
}

// ---------------- kernel 4: finalize first N + loss ----------------
__global__ void __launch_bounds__(256) pass2_kernel(const float* __restrict__ scalars,
                                                    const float* __restrict__ target,
                                                    float* __restrict__ out,
                                                    int write_loss) {
    __shared__ float warp_sums[8];
    __shared__ int sh_last;
    int tid = threadIdx.x;
    int i = blockIdx.x * blockDim.x + tid;

    float sq = 0.0f;
    if (i < NN) {
        float2 a = g_acc2[i];
        float acc = fmaf(-scalars[i], a.y, a.x);
        float ns = out[i] + acc;
        out[i] = ns;
        float d = target[i] - ns;
        sq = d * d;
    }

    #pragma unroll
    for (int o = 16; o > 0; o >>= 1) sq += __shfl_down_sync(0xFFFFFFFFu, sq, o);
    int lane = tid & 31, wid = tid >> 5;
    if (lane == 0) warp_sums[wid] = sq;
    __syncthreads();
    if (wid == 0) {
        float v = (lane < 8) ? warp_sums[lane] : 0.0f;
        #pragma unroll
        for (int o = 4; o > 0; o >>= 1) v += __shfl_down_sync(0xFFFFFFFFu, v, o);
        if (lane == 0) atomicAdd(&g_loss, (double)v);
    }

    // last block writes the loss
    if (tid == 0) {
        __threadfence();
        sh_last = (atomicAdd(&g_done, 1u) == gridDim.x - 1);
    }
    __syncthreads();
    if (sh_last && tid == 0) {
        if (write_loss) out[NE] = (float)(g_loss / (double)NE);
        g_done = 0;   // reset for next replay
    }
}

// ---------------- launcher ----------------
extern "C" void kernel_launch(void* const* d_in, const int* in_sizes, int n_in,
                              void* d_out, int out_size) {
    const int*   node_states = (const int*)  d_in[0];
    const int*   edge_states = (const int*)  d_in[1];
    const float* scalars     = (const float*)d_in[2];
    const int*   edge_index  = (const int*)  d_in[3];
    const int*   brev        = (const int*)  d_in[4];
    const float* batch_sc    = (const float*)d_in[5];
    const int*   train_step  = (const int*)  d_in[7];
    const float* node_emb    = (const float*)d_in[8];
    const float* edge_emb    = (const float*)d_in[9];
    const float* combine_W   = (const float*)d_in[10];
    const float* combine_b   = (const float*)d_in[11];
    const float* keep_W      = (const float*)d_in[12];
    const float* keep_b      = (const float*)d_in[13];
    const float* push_W      = (const float*)d_in[14];
    const float* push_b      = (const float*)d_in[15];
    const float* pushn_W     = (const float*)d_in[16];
    const float* pushn_b     = (const float*)d_in[17];
    const float* inc_W       = (const float*)d_in[18];
    const float* inc_b       = (const float*)d_in[19];

    float* out = (float*)d_out;

    prep_kernel<<<(NE + 255) / 256, 256>>>(node_states, edge_states, scalars);
    tables_kernel<<<32, 128>>>(combine_W, combine_b, node_emb, edge_emb,
                               keep_W, keep_b, push_W, push_b,
                               pushn_W, pushn_b, inc_W, inc_b, train_step);
    pass1_kernel<<<(NE + 255) / 256, 256>>>(edge_index, brev, scalars, batch_sc, out);
    pass2_kernel<<<(NN + 255) / 256, 256>>>(scalars, batch_sc, out,
                                            out_size > NE ? 1 : 0);
}